// round 17
// baseline (speedup 1.0000x reference)
#include <cuda_runtime.h>

// RNNModel: 2-layer tanh RNN + FC, B=2048, T=512, I=8, H=64.
// R16: R15 tensor-core kernel + (1) h hi/lo interleaved in one ull so each
// B-fragment fetch is a single LDS.64 (halves B LDS count; stores -> STS.128),
// and (2) per-term accumulator chains (hh/hl/lh separate) so dependent-mma
// chains shrink from ~12 to 8 with 9 independent chains per warp.
// Same math as R15 (rel_err 7.4e-7): mma.m16n8k8.tf32, 3-term hi/lo split,
// inline x-projection, lag-1 layer pipeline, one __syncthreads per step.

#define BB 2048
#define TT 512
#define ECTA 8
#define NCTA (BB / ECTA)
#define SLOG 2.8853900817779268f   // 2*log2(e)
#define FULLMASK 0xffffffffu

typedef unsigned long long ull;

__device__ __forceinline__ unsigned cvt_tf32(float f) {
    unsigned u; asm("cvt.rna.tf32.f32 %0, %1;" : "=r"(u) : "f"(f)); return u;
}
__device__ __forceinline__ void mma8(float& d0, float& d1, float& d2, float& d3,
                                     unsigned a0, unsigned a1, unsigned a2, unsigned a3,
                                     unsigned b0, unsigned b1) {
    asm volatile("mma.sync.aligned.m16n8k8.row.col.f32.tf32.tf32.f32 "
                 "{%0,%1,%2,%3},{%4,%5,%6,%7},{%8,%9},{%0,%1,%2,%3};"
                 : "+f"(d0), "+f"(d1), "+f"(d2), "+f"(d3)
                 : "r"(a0), "r"(a1), "r"(a2), "r"(a3), "r"(b0), "r"(b1));
}
__device__ __forceinline__ float fast_tanh_scaled(float zs) {
    float e; asm("ex2.approx.f32 %0, %1;" : "=f"(e) : "f"(zs));
    float r; asm("rcp.approx.f32 %0, %1;" : "=f"(r) : "f"(e + 1.f));
    return fmaf(-2.f, r, 1.f);
}

extern __shared__ unsigned smu[];

__global__ void __launch_bounds__(128)
rnn_mma3_kernel(const float* __restrict__ x,
                const float* __restrict__ W_ih0, const float* __restrict__ W_hh0,
                const float* __restrict__ W_ih1, const float* __restrict__ W_hh1,
                const float* __restrict__ b_ih0, const float* __restrict__ b_hh0,
                const float* __restrict__ b_ih1, const float* __restrict__ b_hh1,
                const float* __restrict__ fc_w, const float* __restrict__ fc_b,
                float* __restrict__ out)
{
    unsigned* WLO = smu;                   // 12288 uints (W-lo fragments)
    ull* HBu = (ull*)(smu + 12288);        // 4 buffers x 512 ull: (hi,lo) per [k][e]
    float* SFC = (float*)(smu + 12288 + 4096);   // 32 floats
    float* SXF = SFC + 32;                 // 2 x-buffers x 96 floats

    const int tid = threadIdx.x, w = tid >> 5, lane = tid & 31;
    const int g = lane >> 2, tt = lane & 3, mb = w * 16, ce = blockIdx.x;

    // buffers: 0 = h0 p0, 1 = h0 p1, 2 = h1 p0, 3 = h1 p1
    for (int i = tid; i < 4096; i += 128) ((unsigned*)HBu)[i] = 0u;

    // A-hi fragments (regs) + A-lo (SMEM). m16n8k8 A: rows g,g+8; cols tt,tt+4.
    unsigned Ah0[32], Ah1[32], Ah2[32];
#define BUILDW(AH, WP, MAT)                                                    \
    { _Pragma("unroll")                                                        \
      for (int t = 0; t < 8; t++) {                                            \
        int c0 = 8*t + tt, c1 = c0 + 4;                                        \
        float f0 = WP[(mb+g)*64 + c0] * SLOG;                                  \
        float f1 = WP[(mb+g+8)*64 + c0] * SLOG;                                \
        float f2 = WP[(mb+g)*64 + c1] * SLOG;                                  \
        float f3 = WP[(mb+g+8)*64 + c1] * SLOG;                                \
        unsigned u0=cvt_tf32(f0), u1=cvt_tf32(f1);                             \
        unsigned u2=cvt_tf32(f2), u3=cvt_tf32(f3);                             \
        AH[4*t]=u0; AH[4*t+1]=u1; AH[4*t+2]=u2; AH[4*t+3]=u3;                  \
        uint4 lo;                                                              \
        lo.x = cvt_tf32(f0 - __uint_as_float(u0));                             \
        lo.y = cvt_tf32(f1 - __uint_as_float(u1));                             \
        lo.z = cvt_tf32(f2 - __uint_as_float(u2));                             \
        lo.w = cvt_tf32(f3 - __uint_as_float(u3));                             \
        *(uint4*)&WLO[(((MAT)*4 + w)*8 + t)*128 + lane*4] = lo;                \
      } }
    BUILDW(Ah0, W_hh0, 0)
    BUILDW(Ah1, W_ih1, 1)
    BUILDW(Ah2, W_hh1, 2)
#undef BUILDW

    // W_ih0 rows (scaled) + biases for the inline x-projection.
    float w0g[8], w0g8[8];
    #pragma unroll
    for (int k = 0; k < 8; k++) {
        w0g[k]  = W_ih0[(mb+g)*8 + k]   * SLOG;
        w0g8[k] = W_ih0[(mb+g+8)*8 + k] * SLOG;
    }
    const float b0g  = (b_ih0[mb+g]   + b_hh0[mb+g])   * SLOG;
    const float b0g8 = (b_ih0[mb+g+8] + b_hh0[mb+g+8]) * SLOG;
    const float bj   = (b_ih1[mb+g]   + b_hh1[mb+g])   * SLOG;
    const float bj8  = (b_ih1[mb+g+8] + b_hh1[mb+g+8]) * SLOG;

    // x prefetch setup: threads 0..15 each own (element pe, half ph).
    const int pe = tid >> 1, ph = tid & 1;
    const float* xpf = x + ((size_t)(ce*ECTA + pe) * TT) * 8 + ph * 4;
    const int spfo = pe * 12 + ph * 4;
    if (tid < 16) *(float4*)&SXF[spfo] = *(const float4*)xpf;   // x[0] -> buf0
    xpf += 8;

    __syncthreads();

    const int o = tt*8 + g;                        // B-fragment ull base: [k=tt][e=g]
    const int s0u = (mb+g)*8 + 2*tt;               // store ull index, row g
    const int s1u = (mb+g+8)*8 + 2*tt;             // store ull index, row g+8
    const int sxe0 = tt * 24;

    // Store h fragment: (hi,lo) interleaved; 2 x STS.128 per h-vector.
#define SSTORE(V0, V1, V2, V3, BUF)                                            \
    { unsigned u0=cvt_tf32(V0), u1=cvt_tf32(V1);                               \
      unsigned u2=cvt_tf32(V2), u3=cvt_tf32(V3);                               \
      unsigned v0=cvt_tf32((V0)-__uint_as_float(u0));                          \
      unsigned v1=cvt_tf32((V1)-__uint_as_float(u1));                          \
      unsigned v2=cvt_tf32((V2)-__uint_as_float(u2));                          \
      unsigned v3=cvt_tf32((V3)-__uint_as_float(u3));                          \
      ulonglong2 t0, t1;                                                       \
      t0.x = (ull)u0 | ((ull)v0 << 32);  t0.y = (ull)u1 | ((ull)v1 << 32);     \
      t1.x = (ull)u2 | ((ull)v2 << 32);  t1.y = (ull)u3 | ((ull)v3 << 32);     \
      *(ulonglong2*)&HBu[(BUF)*512 + s0u] = t0;                                \
      *(ulonglong2*)&HBu[(BUF)*512 + s1u] = t1;                                \
    }

#define XDOT(CUR, R0, R1, R2, R3)                                              \
    {                                                                          \
        const float* sx = SXF + (CUR) * 96 + sxe0;                             \
        float4 a0 = *(const float4*)(sx);                                      \
        float4 a1 = *(const float4*)(sx + 4);                                  \
        float4 bb0 = *(const float4*)(sx + 12);                                \
        float4 bb1 = *(const float4*)(sx + 16);                                \
        R0 = b0g;  R1 = b0g;  R2 = b0g8; R3 = b0g8;                            \
        R0 = fmaf(a0.x,w0g[0],R0); R0 = fmaf(a0.y,w0g[1],R0);                  \
        R0 = fmaf(a0.z,w0g[2],R0); R0 = fmaf(a0.w,w0g[3],R0);                  \
        R0 = fmaf(a1.x,w0g[4],R0); R0 = fmaf(a1.y,w0g[5],R0);                  \
        R0 = fmaf(a1.z,w0g[6],R0); R0 = fmaf(a1.w,w0g[7],R0);                  \
        R1 = fmaf(bb0.x,w0g[0],R1); R1 = fmaf(bb0.y,w0g[1],R1);                \
        R1 = fmaf(bb0.z,w0g[2],R1); R1 = fmaf(bb0.w,w0g[3],R1);                \
        R1 = fmaf(bb1.x,w0g[4],R1); R1 = fmaf(bb1.y,w0g[5],R1);                \
        R1 = fmaf(bb1.z,w0g[6],R1); R1 = fmaf(bb1.w,w0g[7],R1);                \
        R2 = fmaf(a0.x,w0g8[0],R2); R2 = fmaf(a0.y,w0g8[1],R2);                \
        R2 = fmaf(a0.z,w0g8[2],R2); R2 = fmaf(a0.w,w0g8[3],R2);                \
        R2 = fmaf(a1.x,w0g8[4],R2); R2 = fmaf(a1.y,w0g8[5],R2);                \
        R2 = fmaf(a1.z,w0g8[6],R2); R2 = fmaf(a1.w,w0g8[7],R2);                \
        R3 = fmaf(bb0.x,w0g8[0],R3); R3 = fmaf(bb0.y,w0g8[1],R3);              \
        R3 = fmaf(bb0.z,w0g8[2],R3); R3 = fmaf(bb0.w,w0g8[3],R3);              \
        R3 = fmaf(bb1.x,w0g8[4],R3); R3 = fmaf(bb1.y,w0g8[5],R3);              \
        R3 = fmaf(bb1.z,w0g8[6],R3); R3 = fmaf(bb1.w,w0g8[7],R3);              \
    }

#define XPREF(NXT)                                                             \
    if (tid < 16) { *(float4*)&SXF[(NXT)*96 + spfo] = *(const float4*)xpf; }   \
    xpf += 8;

    // ---- Peel i=0: h0[0] = tanh(pre[0]) -> buf0 ----
    {
        float p0, p1, p2, p3;
        XDOT(0, p0, p1, p2, p3)
        XPREF(1)
        float h00=fast_tanh_scaled(p0), h01=fast_tanh_scaled(p1);
        float h02=fast_tanh_scaled(p2), h03=fast_tanh_scaled(p3);
        SSTORE(h00,h01,h02,h03, 0)
        __syncthreads();
    }

    float h10, h11, h12, h13;

#define MMAS(D, AHp, B0, B1) \
    mma8(D##0, D##1, D##2, D##3, (AHp)[0],(AHp)[1],(AHp)[2],(AHp)[3], B0, B1);
#define MMAL(D, L, B0, B1) \
    mma8(D##0, D##1, D##2, D##3, (L).x,(L).y,(L).z,(L).w, B0, B1);

    // STEP at iter i: h0[i] = tanh(pre[i] + s*Whh0.h0[i-1]),
    //                 h1[i-1] = tanh(s*b1 + s*Wih1.h0[i-1] + s*Whh1.h1[i-2]).
    // R0/R1 = read buffers (h0/h1), W0/W1 = write buffers.
#define STEP(R0, R1, W0, W1, CUR, NXT, PF)                                     \
    {                                                                          \
        float q0h0, q0h1, q0h2, q0h3;                                          \
        XDOT(CUR, q0h0, q0h1, q0h2, q0h3)                                      \
        if (PF) { XPREF(NXT) }                                                 \
        float q0l0=0,q0l1=0,q0l2=0,q0l3=0, q0w0=0,q0w1=0,q0w2=0,q0w3=0;        \
        float q1h0=bj,q1h1=bj,q1h2=bj8,q1h3=bj8;                               \
        float q1l0=0,q1l1=0,q1l2=0,q1l3=0, q1w0=0,q1w1=0,q1w2=0,q1w3=0;        \
        float q2h0=0,q2h1=0,q2h2=0,q2h3=0, q2l0=0,q2l1=0,q2l2=0,q2l3=0;        \
        float q2w0=0,q2w1=0,q2w2=0,q2w3=0;                                     \
        const ull* Bu0 = HBu + (R0)*512;                                       \
        const ull* Bu1 = HBu + (R1)*512;                                       \
        _Pragma("unroll")                                                      \
        for (int t = 0; t < 8; t++) {                                          \
            ull L0 = Bu0[64*t + o];                                            \
            ull L1 = Bu0[64*t + o + 32];                                       \
            unsigned bh0=(unsigned)L0, bl0=(unsigned)(L0 >> 32);               \
            unsigned bh1=(unsigned)L1, bl1=(unsigned)(L1 >> 32);               \
            uint4 l0 = *(const uint4*)&WLO[((0+w)*8+t)*128 + lane*4];          \
            uint4 l1 = *(const uint4*)&WLO[((4+w)*8+t)*128 + lane*4];          \
            MMAS(q0h, &Ah0[4*t], bh0, bh1)                                     \
            MMAS(q0l, &Ah0[4*t], bl0, bl1)                                     \
            MMAL(q0w, l0, bh0, bh1)                                            \
            MMAS(q1h, &Ah1[4*t], bh0, bh1)                                     \
            MMAS(q1l, &Ah1[4*t], bl0, bl1)                                     \
            MMAL(q1w, l1, bh0, bh1)                                            \
        }                                                                      \
        _Pragma("unroll")                                                      \
        for (int t = 0; t < 8; t++) {                                          \
            ull L0 = Bu1[64*t + o];                                            \
            ull L1 = Bu1[64*t + o + 32];                                       \
            unsigned bh0=(unsigned)L0, bl0=(unsigned)(L0 >> 32);               \
            unsigned bh1=(unsigned)L1, bl1=(unsigned)(L1 >> 32);               \
            uint4 l2 = *(const uint4*)&WLO[((8+w)*8+t)*128 + lane*4];          \
            MMAS(q2h, &Ah2[4*t], bh0, bh1)                                     \
            MMAS(q2l, &Ah2[4*t], bl0, bl1)                                     \
            MMAL(q2w, l2, bh0, bh1)                                            \
        }                                                                      \
        float h00=fast_tanh_scaled(q0h0+q0l0+q0w0);                            \
        float h01=fast_tanh_scaled(q0h1+q0l1+q0w1);                            \
        float h02=fast_tanh_scaled(q0h2+q0l2+q0w2);                            \
        float h03=fast_tanh_scaled(q0h3+q0l3+q0w3);                            \
        h10=fast_tanh_scaled(q1h0+q1l0+q1w0+q2h0+q2l0+q2w0);                   \
        h11=fast_tanh_scaled(q1h1+q1l1+q1w1+q2h1+q2l1+q2w1);                   \
        h12=fast_tanh_scaled(q1h2+q1l2+q1w2+q2h2+q2l2+q2w2);                   \
        h13=fast_tanh_scaled(q1h3+q1l3+q1w3+q2h3+q2l3+q2w3);                   \
        SSTORE(h00,h01,h02,h03, W0)                                            \
        SSTORE(h10,h11,h12,h13, W1)                                            \
        __syncthreads();                                                       \
    }

    // i = 1..510 as 255 pairs, then i = 511.
    for (int it = 0; it < 255; it++) {
        STEP(0, 3, 1, 2, 1, 0, 1)    // i odd:  read h0 buf0, h1 buf3 -> buf1, buf2
        STEP(1, 2, 0, 3, 0, 1, 1)    // i even: read h0 buf1, h1 buf2 -> buf0, buf3
    }
    STEP(0, 3, 1, 2, 1, 0, 0)        // i = 511
#undef STEP
#undef XPREF
#undef XDOT

    // ---- Tail i=512: h1[511] from h0[511] (buf1) and h1[510] (buf2) ----
    {
        float q1h0=bj,q1h1=bj,q1h2=bj8,q1h3=bj8;
        float q1l0=0,q1l1=0,q1l2=0,q1l3=0, q1w0=0,q1w1=0,q1w2=0,q1w3=0;
        float q2h0=0,q2h1=0,q2h2=0,q2h3=0, q2l0=0,q2l1=0,q2l2=0,q2l3=0;
        float q2w0=0,q2w1=0,q2w2=0,q2w3=0;
        const ull* Bu0 = HBu + 1*512;
        const ull* Bu1 = HBu + 2*512;
        #pragma unroll
        for (int t = 0; t < 8; t++) {
            ull L0 = Bu0[64*t + o];
            ull L1 = Bu0[64*t + o + 32];
            unsigned bh0=(unsigned)L0, bl0=(unsigned)(L0 >> 32);
            unsigned bh1=(unsigned)L1, bl1=(unsigned)(L1 >> 32);
            uint4 l1 = *(const uint4*)&WLO[((4+w)*8+t)*128 + lane*4];
            MMAS(q1h, &Ah1[4*t], bh0, bh1)
            MMAS(q1l, &Ah1[4*t], bl0, bl1)
            MMAL(q1w, l1, bh0, bh1)
        }
        #pragma unroll
        for (int t = 0; t < 8; t++) {
            ull L0 = Bu1[64*t + o];
            ull L1 = Bu1[64*t + o + 32];
            unsigned bh0=(unsigned)L0, bl0=(unsigned)(L0 >> 32);
            unsigned bh1=(unsigned)L1, bl1=(unsigned)(L1 >> 32);
            uint4 l2 = *(const uint4*)&WLO[((8+w)*8+t)*128 + lane*4];
            MMAS(q2h, &Ah2[4*t], bh0, bh1)
            MMAS(q2l, &Ah2[4*t], bl0, bl1)
            MMAL(q2w, l2, bh0, bh1)
        }
        h10 = fast_tanh_scaled(q1h0+q1l0+q1w0+q2h0+q2l0+q2w0);
        h11 = fast_tanh_scaled(q1h1+q1l1+q1w1+q2h1+q2l1+q2w1);
        h12 = fast_tanh_scaled(q1h2+q1l2+q1w2+q2h2+q2l2+q2w2);
        h13 = fast_tanh_scaled(q1h3+q1l3+q1w3+q2h3+q2l3+q2w3);
    }
#undef MMAS
#undef MMAL
#undef SSTORE

    // ---- FC: out[ce*8+e] = sum_j h1[511][j]*fc_w[j] + fc_b ----
    {
        float fw0 = fc_w[mb+g], fw8 = fc_w[mb+g+8];
        float p0 = h10*fw0 + h12*fw8;        // element e = 2tt
        float p1 = h11*fw0 + h13*fw8;        // element e = 2tt+1
        p0 += __shfl_xor_sync(FULLMASK,p0,4);  p1 += __shfl_xor_sync(FULLMASK,p1,4);
        p0 += __shfl_xor_sync(FULLMASK,p0,8);  p1 += __shfl_xor_sync(FULLMASK,p1,8);
        p0 += __shfl_xor_sync(FULLMASK,p0,16); p1 += __shfl_xor_sync(FULLMASK,p1,16);
        if (g == 0) { SFC[w*8 + 2*tt] = p0; SFC[w*8 + 2*tt + 1] = p1; }
        __syncthreads();
        if (tid < 8)
            out[ce*8 + tid] = SFC[tid] + SFC[8+tid] + SFC[16+tid] + SFC[24+tid] + fc_b[0];
    }
}

extern "C" void kernel_launch(void* const* d_in, const int* in_sizes, int n_in,
                              void* d_out, int out_size)
{
    const float* x     = (const float*)d_in[0];
    const float* W_ih0 = (const float*)d_in[1];
    const float* W_hh0 = (const float*)d_in[2];
    const float* b_ih0 = (const float*)d_in[3];
    const float* b_hh0 = (const float*)d_in[4];
    const float* W_ih1 = (const float*)d_in[5];
    const float* W_hh1 = (const float*)d_in[6];
    const float* b_ih1 = (const float*)d_in[7];
    const float* b_hh1 = (const float*)d_in[8];
    const float* fc_w  = (const float*)d_in[9];
    const float* fc_b  = (const float*)d_in[10];
    float* out = (float*)d_out;

    // smem: 12288 (WLO) + 4096 (HBu) + 32 (SFC) + 192 (SXF) unsigned = 66432 B
    const int smem_bytes = (12288 + 4096 + 32 + 192) * 4;
    cudaFuncSetAttribute(rnn_mma3_kernel,
                         cudaFuncAttributeMaxDynamicSharedMemorySize, smem_bytes);

    rnn_mma3_kernel<<<NCTA, 128, smem_bytes>>>(
        x, W_ih0, W_hh0, W_ih1, W_hh1,
        b_ih0, b_hh0, b_ih1, b_hh1, fc_w, fc_b, out);
}